// round 2
// baseline (speedup 1.0000x reference)
#include <cuda_runtime.h>
#include <math.h>

// HouseholderRoPE: B=2,H=16,T=8192,D=64,M=8
// out = concat(q_rot, k_rot), float32, 2*B*H*T*D elements.

#define BB 2
#define HH 16
#define TT 8192
#define DD 64
#define MM 8
#define EPSF 1e-8f

#define TPB 256
#define T_PER_BLOCK 32   // 8 warps * 4 t-rows per warp

// Scratch (device globals: allocation-free per harness rules)
__device__ float g_Y[HH * MM * DD];   // normalized Householder vectors, [h][m][d]
__device__ float g_W[HH * MM * DD];   // W = Y*T (compact WY), [h][m][d] = column m of W
__device__ float g_cs[TT * DD];       // per t: 32 pairs * (cos,sin) interleaved

// ---------------------------------------------------------------------------
// Setup kernel 1: per-head normalize V -> Y, build T (8x8 upper-tri), W = Y*T.
// One block per head, 512 threads (m = tid/64, d = tid%64).
//
// Product applied by the reference is Q = P0*P1*...*P7 (m = M-1 .. 0 loop,
// z updated in place => leftmost factor applied last = P0).
// Compact WY: Q = I - Y T Y^T with
//   T[j][j] = 2,  T[i][j] = -2 * sum_{k=i..j-1} T[i][k] * (u_k . u_j), i<j.
// ---------------------------------------------------------------------------
__global__ void setup_head_kernel(const float* __restrict__ V) {
    __shared__ float su[MM][DD];
    __shared__ float sq2[MM][DD];
    __shared__ float sG[MM][MM];
    __shared__ float sT[MM][MM];
    __shared__ float rnorm[MM];

    const int h   = blockIdx.x;
    const int tid = threadIdx.x;
    const int m   = tid >> 6;
    const int d   = tid & 63;

    float v = V[(h * MM + m) * DD + d];
    sq2[m][d] = v * v;
    __syncthreads();

    if (tid < MM) {
        float s = EPSF * EPSF;
        #pragma unroll 8
        for (int i = 0; i < DD; i++) s += sq2[tid][i];
        rnorm[tid] = 1.0f / sqrtf(s);
    }
    __syncthreads();

    float u = v * rnorm[m];
    su[m][d] = u;
    g_Y[(h * MM + m) * DD + d] = u;
    __syncthreads();

    // Gram matrix G[i][j] = u_i . u_j  (threads 0..63)
    if (tid < 64) {
        int i  = tid >> 3;
        int jj = tid & 7;
        float s = 0.0f;
        #pragma unroll 8
        for (int dd = 0; dd < DD; dd++) s += su[i][dd] * su[jj][dd];
        sG[i][jj] = s;
    }
    __syncthreads();

    if (tid == 0) {
        for (int i = 0; i < MM; i++)
            for (int j2 = 0; j2 < MM; j2++) sT[i][j2] = 0.0f;
        sT[0][0] = 2.0f;
        for (int j2 = 1; j2 < MM; j2++) {
            for (int i = 0; i < j2; i++) {
                float acc = 0.0f;
                for (int kk = i; kk < j2; kk++) acc += sT[i][kk] * sG[kk][j2];
                sT[i][j2] = -2.0f * acc;
            }
            sT[j2][j2] = 2.0f;
        }
    }
    __syncthreads();

    // W[:,m] = sum_{k<=m} u_k * T[k][m]   (thread (m,d))
    float w = 0.0f;
    #pragma unroll
    for (int kk = 0; kk <= m; kk++) w += su[kk][d] * sT[kk][m];
    g_W[(h * MM + m) * DD + d] = w;
}

// ---------------------------------------------------------------------------
// Setup kernel 2: cos/sin table. Accurate mod-2pi reduction in double so the
// result matches jnp.cos/sin on the fp32 angle even under --use_fast_math.
// ---------------------------------------------------------------------------
__global__ void setup_cs_kernel(const float* __restrict__ pos,
                                const float* __restrict__ freq) {
    int idx = blockIdx.x * blockDim.x + threadIdx.x;
    if (idx >= TT * 32) return;
    int t = idx >> 5;
    int p = idx & 31;
    float ang = pos[t] * freq[p];          // exactly as reference (fp32 product)
    double a  = (double)ang;
    double kq = floor(a * 0.15915494309189535);   // 1/(2*pi)
    double r  = a - kq * 6.283185307179586;
    float rf  = (float)r;
    g_cs[t * 64 + 2 * p]     = cosf(rf);   // |rf| < 2*pi: accurate even as __cosf
    g_cs[t * 64 + 2 * p + 1] = sinf(rf);
}

// ---------------------------------------------------------------------------
// Main kernel: 8 lanes per row, 4 rows (t positions) per warp, q and k of the
// same t processed together. z_bar = z - W * (Y^T z), then RoPE from table.
// q/k/out are touched exactly once -> streaming (.cs) loads/stores; the 2MB
// cos/sin table is re-read 32x and should stay L2-resident.
// ---------------------------------------------------------------------------
__global__ void __launch_bounds__(TPB) hh_rope_kernel(
    const float* __restrict__ q, const float* __restrict__ k,
    float* __restrict__ out)
{
    __shared__ float sY[MM * DD];
    __shared__ float sW[MM * DD];

    const int nTB = TT / T_PER_BLOCK;           // 256
    const int bh  = blockIdx.x / nTB;           // 0..B*H-1
    const int tb  = blockIdx.x % nTB;
    const int h   = bh & (HH - 1);

    const int tid = threadIdx.x;
    for (int i = tid; i < MM * DD; i += TPB) {
        sY[i] = g_Y[h * MM * DD + i];
        sW[i] = g_W[h * MM * DD + i];
    }
    __syncthreads();

    const int lane = tid & 31;
    const int warp = tid >> 5;
    const int j    = lane & 7;    // d-slice within row
    const int g    = lane >> 3;   // which of 4 t rows in this warp

    const int t = tb * T_PER_BLOCK + warp * 4 + g;
    const size_t rowf4 = ((size_t)bh * TT + t) * (DD / 4);

    const float4* q4 = (const float4*)q;
    const float4* k4 = (const float4*)k;

    // lane j owns elements [4j..4j+3] and [32+4j..32+4j+3]
    float4 qa = __ldcs(&q4[rowf4 + j]);
    float4 qb = __ldcs(&q4[rowf4 + 8 + j]);
    float4 ka = __ldcs(&k4[rowf4 + j]);
    float4 kb = __ldcs(&k4[rowf4 + 8 + j]);

    // s = Y^T z : per-lane partials over 8 owned elements
    float sq[MM], sk[MM];
    #pragma unroll
    for (int m = 0; m < MM; m++) {
        float4 ya = *(const float4*)&sY[m * DD + 4 * j];
        float4 yb = *(const float4*)&sY[m * DD + 32 + 4 * j];
        sq[m] = qa.x * ya.x + qa.y * ya.y + qa.z * ya.z + qa.w * ya.w
              + qb.x * yb.x + qb.y * yb.y + qb.z * yb.z + qb.w * yb.w;
        sk[m] = ka.x * ya.x + ka.y * ya.y + ka.z * ya.z + ka.w * ya.w
              + kb.x * yb.x + kb.y * yb.y + kb.z * yb.z + kb.w * yb.w;
    }

    // Butterfly all-reduce across the 8 lanes of each row group (xor 1,2,4
    // stays in-group; all 4 row groups reduce in the same shfl instructions).
    #pragma unroll
    for (int off = 1; off < 8; off <<= 1) {
        #pragma unroll
        for (int m = 0; m < MM; m++) {
            sq[m] += __shfl_xor_sync(0xffffffffu, sq[m], off);
            sk[m] += __shfl_xor_sync(0xffffffffu, sk[m], off);
        }
    }

    // z -= W s
    #pragma unroll
    for (int m = 0; m < MM; m++) {
        float4 wa = *(const float4*)&sW[m * DD + 4 * j];
        float4 wb = *(const float4*)&sW[m * DD + 32 + 4 * j];
        qa.x -= wa.x * sq[m]; qa.y -= wa.y * sq[m];
        qa.z -= wa.z * sq[m]; qa.w -= wa.w * sq[m];
        qb.x -= wb.x * sq[m]; qb.y -= wb.y * sq[m];
        qb.z -= wb.z * sq[m]; qb.w -= wb.w * sq[m];
        ka.x -= wa.x * sk[m]; ka.y -= wa.y * sk[m];
        ka.z -= wa.z * sk[m]; ka.w -= wa.w * sk[m];
        kb.x -= wb.x * sk[m]; kb.y -= wb.y * sk[m];
        kb.z -= wb.z * sk[m]; kb.w -= wb.w * sk[m];
    }

    // RoPE: lane j's elements map to pairs (2j,2j+1) and (16+2j,16+2j+1);
    // table stores (cos,sin) interleaved per pair -> one float4 covers 2 pairs.
    const float4* cs4 = (const float4*)g_cs;
    float4 ca = cs4[(size_t)t * 16 + j];
    float4 cb = cs4[(size_t)t * 16 + 8 + j];

    // rotate in place (even' = e*c - o*s ; odd' = e*s + o*c)
    {
        float e, o;
        e = qa.x; o = qa.y; qa.x = e * ca.x - o * ca.y; qa.y = e * ca.y + o * ca.x;
        e = qa.z; o = qa.w; qa.z = e * ca.z - o * ca.w; qa.w = e * ca.w + o * ca.z;
        e = qb.x; o = qb.y; qb.x = e * cb.x - o * cb.y; qb.y = e * cb.y + o * cb.x;
        e = qb.z; o = qb.w; qb.z = e * cb.z - o * cb.w; qb.w = e * cb.w + o * cb.z;
        e = ka.x; o = ka.y; ka.x = e * ca.x - o * ca.y; ka.y = e * ca.y + o * ca.x;
        e = ka.z; o = ka.w; ka.z = e * ca.z - o * ca.w; ka.w = e * ca.w + o * ca.z;
        e = kb.x; o = kb.y; kb.x = e * cb.x - o * cb.y; kb.y = e * cb.y + o * cb.x;
        e = kb.z; o = kb.w; kb.z = e * cb.z - o * cb.w; kb.w = e * cb.w + o * cb.z;
    }

    float4* o4 = (float4*)out;
    const size_t koff = (size_t)BB * HH * TT * (DD / 4);
    __stcs(&o4[rowf4 + j],            qa);
    __stcs(&o4[rowf4 + 8 + j],        qb);
    __stcs(&o4[koff + rowf4 + j],     ka);
    __stcs(&o4[koff + rowf4 + 8 + j], kb);
}

// ---------------------------------------------------------------------------
extern "C" void kernel_launch(void* const* d_in, const int* in_sizes, int n_in,
                              void* d_out, int out_size) {
    const float* q    = (const float*)d_in[0];
    const float* k    = (const float*)d_in[1];
    const float* V    = (const float*)d_in[2];
    const float* pos  = (const float*)d_in[3];
    const float* freq = (const float*)d_in[4];
    float* out = (float*)d_out;

    setup_head_kernel<<<HH, 512>>>(V);
    setup_cs_kernel<<<(TT * 32 + 255) / 256, 256>>>(pos, freq);
    hh_rope_kernel<<<BB * HH * (TT / T_PER_BLOCK), TPB>>>(q, k, out);
}